// round 8
// baseline (speedup 1.0000x reference)
#include <cuda_runtime.h>
#include <cuda_bf16.h>
#include <mma.h>
#include <cstdint>

using namespace nvcuda;
using u64 = unsigned long long;
#define FULL_MASK 0xFFFFFFFFu

constexpr int IN_DIM = 256;
constexpr int D = 32;
constexpr float LN_EPS = 1e-5f;

constexpr int TILE_RF  = 64;           // rf rows per block tile
constexpr int ASTRIDE  = 264;          // bf16 elements per smem row (528 B, ldmatrix-friendly)
constexpr int THREADS1 = 128;          // 4 warps

__device__ float g_scratch[65536 * 3 * 32];   // [rf][32] projection pre-bias

// smem byte offsets (kernel 1)
constexpr int OFF_AHI = 0;
constexpr int OFF_ALO = OFF_AHI + TILE_RF * ASTRIDE * 2;     // 33792
constexpr int OFF_BHI = OFF_ALO + TILE_RF * ASTRIDE * 2;     // 67584
constexpr int OFF_BLO = OFF_BHI + D * ASTRIDE * 2;           // 84480
constexpr int OFF_CB  = OFF_BLO + D * ASTRIDE * 2;           // 101376
constexpr int SMEM1   = OFF_CB + 4 * 16 * 32 * 4;            // 109568

__device__ __forceinline__ void split4(float4 v, uint2& hi, uint2& lo) {
    __nv_bfloat162 h01 = __floats2bfloat162_rn(v.x, v.y);
    __nv_bfloat162 h23 = __floats2bfloat162_rn(v.z, v.w);
    float lx = v.x - __low2float(h01),  ly = v.y - __high2float(h01);
    float lz = v.z - __low2float(h23),  lw = v.w - __high2float(h23);
    __nv_bfloat162 l01 = __floats2bfloat162_rn(lx, ly);
    __nv_bfloat162 l23 = __floats2bfloat162_rn(lz, lw);
    hi.x = *reinterpret_cast<uint32_t*>(&h01);
    hi.y = *reinterpret_cast<uint32_t*>(&h23);
    lo.x = *reinterpret_cast<uint32_t*>(&l01);
    lo.y = *reinterpret_cast<uint32_t*>(&l23);
}

// ================= kernel 1: projection GEMM via wmma (bf16 hi/lo split) =================
__global__ __launch_bounds__(THREADS1, 2)
void proj_kernel(const float* __restrict__ f1, const float* __restrict__ f4,
                 const float* __restrict__ fD, const float* __restrict__ Wp,
                 int nrf, int ntiles)
{
    extern __shared__ char sm[];
    __nv_bfloat16* Ahi = reinterpret_cast<__nv_bfloat16*>(sm + OFF_AHI);
    __nv_bfloat16* Alo = reinterpret_cast<__nv_bfloat16*>(sm + OFF_ALO);
    __nv_bfloat16* Bhi = reinterpret_cast<__nv_bfloat16*>(sm + OFF_BHI);
    __nv_bfloat16* Blo = reinterpret_cast<__nv_bfloat16*>(sm + OFF_BLO);
    float*         cbf = reinterpret_cast<float*>(sm + OFF_CB);

    const int tid = threadIdx.x, lane = tid & 31, w = tid >> 5;

    // ---- stage Wp hi/lo once: 32x256 f32 = 2048 float4 ----
    #pragma unroll
    for (int t = 0; t < 16; t++) {
        int i = tid + t * THREADS1;           // float4 slot: n*64 + c4
        int n = i >> 6, c4 = i & 63;
        float4 v = reinterpret_cast<const float4*>(Wp)[i];
        uint2 hi, lo;
        split4(v, hi, lo);
        *reinterpret_cast<uint2*>(&Bhi[n * ASTRIDE + c4 * 4]) = hi;
        *reinterpret_cast<uint2*>(&Blo[n * ASTRIDE + c4 * 4]) = lo;
    }
    __syncthreads();

    for (int tile = blockIdx.x; tile < ntiles; tile += gridDim.x) {
        // ---- stage A tile: 64 rf x 256 k, f32 -> bf16 hi/lo ----
        #pragma unroll
        for (int t = 0; t < 32; t++) {
            int i = tid + t * THREADS1;       // float4 slot: rf_l*64 + c4
            int rf_l = i >> 6, c4 = i & 63;
            int rf_g = tile * TILE_RF + rf_l;
            float4 v = make_float4(0.f, 0.f, 0.f, 0.f);
            if (rf_g < nrf) {
                int row = rf_g / 3, ft = rf_g - 3 * row;
                const float* src = (ft == 0) ? f1 : (ft == 1) ? f4 : fD;
                v = reinterpret_cast<const float4*>(src)[row * 64 + c4];
            }
            uint2 hi, lo;
            split4(v, hi, lo);
            *reinterpret_cast<uint2*>(&Ahi[rf_l * ASTRIDE + c4 * 4]) = hi;
            *reinterpret_cast<uint2*>(&Alo[rf_l * ASTRIDE + c4 * 4]) = lo;
        }
        __syncthreads();

        // ---- compute: warp w -> rows [16w, 16w+16) ----
        {
            wmma::fragment<wmma::accumulator, 16, 16, 16, float> C[2];
            wmma::fill_fragment(C[0], 0.f);
            wmma::fill_fragment(C[1], 0.f);
            wmma::fragment<wmma::matrix_a, 16, 16, 16, __nv_bfloat16, wmma::row_major> ah, al;
            wmma::fragment<wmma::matrix_b, 16, 16, 16, __nv_bfloat16, wmma::col_major> bh, bl;

            const __nv_bfloat16* Aw_h = Ahi + w * 16 * ASTRIDE;
            const __nv_bfloat16* Aw_l = Alo + w * 16 * ASTRIDE;
            #pragma unroll
            for (int k = 0; k < 16; k++) {
                wmma::load_matrix_sync(ah, Aw_h + k * 16, ASTRIDE);
                wmma::load_matrix_sync(al, Aw_l + k * 16, ASTRIDE);
                #pragma unroll
                for (int n = 0; n < 2; n++) {
                    wmma::load_matrix_sync(bh, Bhi + n * 16 * ASTRIDE + k * 16, ASTRIDE);
                    wmma::load_matrix_sync(bl, Blo + n * 16 * ASTRIDE + k * 16, ASTRIDE);
                    wmma::mma_sync(C[n], ah, bh, C[n]);
                    wmma::mma_sync(C[n], al, bh, C[n]);
                    wmma::mma_sync(C[n], ah, bl, C[n]);
                }
            }

            int rf0 = tile * TILE_RF + w * 16;
            if (rf0 + 16 <= nrf) {
                wmma::store_matrix_sync(g_scratch + (size_t)rf0 * 32,      C[0], 32, wmma::mem_row_major);
                wmma::store_matrix_sync(g_scratch + (size_t)rf0 * 32 + 16, C[1], 32, wmma::mem_row_major);
            } else if (rf0 < nrf) {
                float* cb = cbf + w * 512;
                wmma::store_matrix_sync(cb,      C[0], 32, wmma::mem_row_major);
                wmma::store_matrix_sync(cb + 16, C[1], 32, wmma::mem_row_major);
                __syncwarp();
                #pragma unroll
                for (int r = 0; r < 16; r++)
                    if (rf0 + r < nrf)
                        g_scratch[(size_t)(rf0 + r) * 32 + lane] = cb[r * 32 + lane];
            }
        }
        __syncthreads();   // compute done before next tile's staging overwrites A
    }
}

// ================= kernel 2: epilogue (LN + attention + MLP) =================
constexpr int WSTRIDE = 36;

__device__ __forceinline__ void ffma2(u64& d, u64 a, u64 b) {
    asm("fma.rn.f32x2 %0, %1, %2, %0;" : "+l"(d) : "l"(a), "l"(b));
}
__device__ __forceinline__ float hsum2(u64 a, u64 b) {
    return __uint_as_float((unsigned)a) + __uint_as_float((unsigned)(a >> 32))
         + __uint_as_float((unsigned)b) + __uint_as_float((unsigned)(b >> 32));
}
__device__ __forceinline__ float wsum(float v) {
    v += __shfl_xor_sync(FULL_MASK, v, 16);
    v += __shfl_xor_sync(FULL_MASK, v, 8);
    v += __shfl_xor_sync(FULL_MASK, v, 4);
    v += __shfl_xor_sync(FULL_MASK, v, 2);
    v += __shfl_xor_sync(FULL_MASK, v, 1);
    return v;
}

__global__ __launch_bounds__(256)
void epi_kernel(const float* __restrict__ bp,
                const float* __restrict__ ln_g, const float* __restrict__ ln_b,
                const float* __restrict__ Wq,  const float* __restrict__ bq,
                const float* __restrict__ Wk,  const float* __restrict__ bk,
                const float* __restrict__ Wv,  const float* __restrict__ bv,
                const float* __restrict__ Wo1, const float* __restrict__ bo1,
                const float* __restrict__ Wo2, const float* __restrict__ bo2,
                float* __restrict__ out, int B)
{
    __shared__ __align__(16) float w5[5 * D * WSTRIDE];
    __shared__ __align__(16) float xbuf[8][3][D];
    __shared__ __align__(16) float pooled[8][D];
    __shared__ __align__(16) float o1s[8][D];

    const int tid = threadIdx.x, lane = tid & 31, w = tid >> 5;

    for (int i = tid; i < D * D; i += 256) {
        int jj = i >> 5, dd = i & 31;
        int o = jj * WSTRIDE + dd;
        w5[0 * D * WSTRIDE + o] = Wq [i];
        w5[1 * D * WSTRIDE + o] = Wk [i];
        w5[2 * D * WSTRIDE + o] = Wv [i];
        w5[3 * D * WSTRIDE + o] = Wo1[i];
        w5[4 * D * WSTRIDE + o] = Wo2[i];
    }
    const float bp_l  = bp [lane];
    const float g_l   = ln_g[lane];
    const float b_l   = ln_b[lane];
    const float bq_l  = bq [lane];
    const float bk_l  = bk [lane];
    const float bv_l  = bv [lane];
    const float bo1_l = bo1[lane];
    const float bo2_l = bo2[lane];
    __syncthreads();

    for (int row = blockIdx.x * 8 + w; row < B; row += gridDim.x * 8) {
        // ---- bias + relu + LayerNorm ----
        #pragma unroll
        for (int s = 0; s < 3; s++) {
            float h = g_scratch[(size_t)(row * 3 + s) * D + lane] + bp_l;
            h = fmaxf(h, 0.f);
            float mu  = wsum(h) * (1.f / 32.f);
            float dv  = h - mu;
            float var = wsum(dv * dv) * (1.f / 32.f);
            xbuf[w][s][lane] = g_l * dv * rsqrtf(var + LN_EPS) + b_l;
        }
        __syncwarp();

        // ---- QKV ----
        float qkvr[3][3];
        float bias3[3] = { bq_l, bk_l, bv_l };
        #pragma unroll
        for (int mat = 0; mat < 3; mat++) {
            const ulonglong2* wrow = reinterpret_cast<const ulonglong2*>(
                w5 + mat * D * WSTRIDE + lane * WSTRIDE);
            u64 a0[3] = {0ull,0ull,0ull}, a1[3] = {0ull,0ull,0ull};
            #pragma unroll
            for (int c = 0; c < 8; c++) {
                ulonglong2 wv = wrow[c];
                #pragma unroll
                for (int ss = 0; ss < 3; ss++) {
                    ulonglong2 xv = reinterpret_cast<const ulonglong2*>(xbuf[w][ss])[c];
                    ffma2(a0[ss], wv.x, xv.x);
                    ffma2(a1[ss], wv.y, xv.y);
                }
            }
            #pragma unroll
            for (int ss = 0; ss < 3; ss++)
                qkvr[mat][ss] = hsum2(a0[ss], a1[ss]) + bias3[mat];
        }

        // ---- attention + softmax + pool ----
        const float scale = 0.17677669529663687f;   // 1/sqrt(32)
        float att[3][3];
        #pragma unroll
        for (int ss = 0; ss < 3; ss++)
            #pragma unroll
            for (int tt = 0; tt < 3; tt++)
                att[ss][tt] = wsum(qkvr[0][ss] * qkvr[1][tt]) * scale;

        float pool = 0.f;
        #pragma unroll
        for (int ss = 0; ss < 3; ss++) {
            float m  = fmaxf(att[ss][0], fmaxf(att[ss][1], att[ss][2]));
            float e0 = __expf(att[ss][0] - m);
            float e1 = __expf(att[ss][1] - m);
            float e2 = __expf(att[ss][2] - m);
            float ri = 1.f / (e0 + e1 + e2);
            pool += (e0 * qkvr[2][0] + e1 * qkvr[2][1] + e2 * qkvr[2][2]) * ri;
        }
        pool *= (1.f / 3.f);
        pooled[w][lane] = pool;
        __syncwarp();

        // ---- O1 ----
        {
            const ulonglong2* pv = reinterpret_cast<const ulonglong2*>(pooled[w]);
            const ulonglong2* w1 = reinterpret_cast<const ulonglong2*>(
                w5 + 3 * D * WSTRIDE + lane * WSTRIDE);
            u64 a0 = 0ull, a1 = 0ull;
            #pragma unroll
            for (int c = 0; c < 8; c++) {
                ulonglong2 pvv = pv[c], wv = w1[c];
                ffma2(a0, wv.x, pvv.x);
                ffma2(a1, wv.y, pvv.y);
            }
            o1s[w][lane] = fmaxf(hsum2(a0, a1) + bo1_l, 0.f);
        }
        __syncwarp();

        // ---- O2 + residual ----
        {
            const ulonglong2* ov = reinterpret_cast<const ulonglong2*>(o1s[w]);
            const ulonglong2* w2 = reinterpret_cast<const ulonglong2*>(
                w5 + 4 * D * WSTRIDE + lane * WSTRIDE);
            u64 a0 = 0ull, a1 = 0ull;
            #pragma unroll
            for (int c = 0; c < 8; c++) {
                ulonglong2 ovv = ov[c], wv = w2[c];
                ffma2(a0, wv.x, ovv.x);
                ffma2(a1, wv.y, ovv.y);
            }
            out[(size_t)row * D + lane] = hsum2(a0, a1) + bo2_l + pool;
        }
        __syncwarp();
    }
}

// ================= launch =================
extern "C" void kernel_launch(void* const* d_in, const int* in_sizes, int n_in,
                              void* d_out, int out_size)
{
    const float* f1   = (const float*)d_in[0];
    const float* f4   = (const float*)d_in[1];
    const float* fD   = (const float*)d_in[2];
    const float* Wp   = (const float*)d_in[3];
    const float* bp   = (const float*)d_in[4];
    const float* ln_g = (const float*)d_in[5];
    const float* ln_b = (const float*)d_in[6];
    const float* Wq   = (const float*)d_in[7];
    const float* bq   = (const float*)d_in[8];
    const float* Wk   = (const float*)d_in[9];
    const float* bk   = (const float*)d_in[10];
    const float* Wv   = (const float*)d_in[11];
    const float* bv   = (const float*)d_in[12];
    const float* Wo1  = (const float*)d_in[13];
    const float* bo1  = (const float*)d_in[14];
    const float* Wo2  = (const float*)d_in[15];
    const float* bo2  = (const float*)d_in[16];

    const int B = in_sizes[0] / IN_DIM;
    const int nrf = B * 3;
    const int ntiles = (nrf + TILE_RF - 1) / TILE_RF;

    cudaFuncSetAttribute(proj_kernel, cudaFuncAttributeMaxDynamicSharedMemorySize, SMEM1);

    int grid1 = ntiles < 304 ? ntiles : 304;    // 2 blocks x 152 SMs
    proj_kernel<<<grid1, THREADS1, SMEM1>>>(f1, f4, fD, Wp, nrf, ntiles);

    int grid2 = (B + 7) / 8;
    if (grid2 > 1216) grid2 = 1216;
    epi_kernel<<<grid2, 256>>>(bp, ln_g, ln_b, Wq, bq, Wk, bk, Wv, bv,
                               Wo1, bo1, Wo2, bo2, (float*)d_out, B);
}

// round 9
// speedup vs baseline: 1.7847x; 1.7847x over previous
#include <cuda_runtime.h>
#include <cuda_bf16.h>
#include <mma.h>
#include <cstdint>

using namespace nvcuda;
using u64 = unsigned long long;
#define FULL_MASK 0xFFFFFFFFu

constexpr int IN_DIM = 256;
constexpr int D = 32;
constexpr float LN_EPS = 1e-5f;

constexpr int TILE_RF   = 128;         // rf rows per block tile (nrf % 128 == 0)
constexpr int KH        = 128;         // k-half size
constexpr int ASTRIDE   = 136;         // bf16 elems per A row (272 B; rows 4 banks apart)
constexpr int BSTRIDE   = 264;         // bf16 elems per B row (full K)
constexpr int THREADS1  = 256;

__device__ float g_scratch[65536 * 3 * 32];   // [rf][32] projection pre-bias

// smem byte offsets (kernel 1)
constexpr int OFF_AHI = 0;                                   // 128*136*2 = 34816
constexpr int OFF_ALO = OFF_AHI + TILE_RF * ASTRIDE * 2;
constexpr int OFF_BHI = OFF_ALO + TILE_RF * ASTRIDE * 2;     // 32*264*2 = 16896
constexpr int OFF_BLO = OFF_BHI + D * BSTRIDE * 2;
constexpr int SMEM1   = OFF_BLO + D * BSTRIDE * 2;           // 103424

__device__ __forceinline__ void split4(float4 v, uint2& hi, uint2& lo) {
    __nv_bfloat162 h01 = __floats2bfloat162_rn(v.x, v.y);
    __nv_bfloat162 h23 = __floats2bfloat162_rn(v.z, v.w);
    float lx = v.x - __low2float(h01),  ly = v.y - __high2float(h01);
    float lz = v.z - __low2float(h23),  lw = v.w - __high2float(h23);
    __nv_bfloat162 l01 = __floats2bfloat162_rn(lx, ly);
    __nv_bfloat162 l23 = __floats2bfloat162_rn(lz, lw);
    hi.x = *reinterpret_cast<uint32_t*>(&h01);
    hi.y = *reinterpret_cast<uint32_t*>(&h23);
    lo.x = *reinterpret_cast<uint32_t*>(&l01);
    lo.y = *reinterpret_cast<uint32_t*>(&l23);
}

// ================= kernel 1: projection GEMM via wmma, k-split, pipelined =================
__global__ __launch_bounds__(THREADS1, 2)
void proj_kernel(const float* __restrict__ f1, const float* __restrict__ f4,
                 const float* __restrict__ fD, const float* __restrict__ Wp,
                 int nrf, int ntiles)
{
    extern __shared__ char sm[];
    __nv_bfloat16* Ahi = reinterpret_cast<__nv_bfloat16*>(sm + OFF_AHI);
    __nv_bfloat16* Alo = reinterpret_cast<__nv_bfloat16*>(sm + OFF_ALO);
    __nv_bfloat16* Bhi = reinterpret_cast<__nv_bfloat16*>(sm + OFF_BHI);
    __nv_bfloat16* Blo = reinterpret_cast<__nv_bfloat16*>(sm + OFF_BLO);

    const int tid = threadIdx.x, lane = tid & 31, w = tid >> 5;

    // ---- stage Wp hi/lo once (full K): 2048 float4 ----
    #pragma unroll
    for (int t = 0; t < 8; t++) {
        int i = tid + t * THREADS1;           // float4 slot: n*64 + c4
        int n = i >> 6, c4 = i & 63;
        float4 v = reinterpret_cast<const float4*>(Wp)[i];
        uint2 hi, lo;
        split4(v, hi, lo);
        *reinterpret_cast<uint2*>(&Bhi[n * BSTRIDE + c4 * 4]) = hi;
        *reinterpret_cast<uint2*>(&Blo[n * BSTRIDE + c4 * 4]) = lo;
    }

    // slot decomposition for a k-half: i = tid + t*256 (t<16); rf_l = i>>5, c4 = i&31
    // global float4 index into f: row*64 + half*32 + c4
    auto ldg_half = [&](int tile, int half, float4 (&buf)[16]) {
        #pragma unroll
        for (int t = 0; t < 16; t++) {
            int i = tid + t * THREADS1;
            int rf_l = i >> 5, c4 = i & 31;
            int rf_g = tile * TILE_RF + rf_l;
            int row = rf_g / 3, ft = rf_g - 3 * row;
            const float* src = (ft == 0) ? f1 : (ft == 1) ? f4 : fD;
            buf[t] = reinterpret_cast<const float4*>(src)[row * 64 + half * 32 + c4];
        }
    };
    auto cvt_half = [&](float4 (&buf)[16]) {
        #pragma unroll
        for (int t = 0; t < 16; t++) {
            int i = tid + t * THREADS1;
            int rf_l = i >> 5, c4 = i & 31;
            uint2 hi, lo;
            split4(buf[t], hi, lo);
            *reinterpret_cast<uint2*>(&Ahi[rf_l * ASTRIDE + c4 * 4]) = hi;
            *reinterpret_cast<uint2*>(&Alo[rf_l * ASTRIDE + c4 * 4]) = lo;
        }
    };

    float4 buf[16];
    int tile0 = blockIdx.x;
    if (tile0 < ntiles) ldg_half(tile0, 0, buf);   // prologue
    __syncthreads();                                // B staged

    for (int tile = tile0; tile < ntiles; tile += gridDim.x) {
        wmma::fragment<wmma::accumulator, 16, 16, 16, float> C[2];
        wmma::fill_fragment(C[0], 0.f);
        wmma::fill_fragment(C[1], 0.f);
        wmma::fragment<wmma::matrix_a, 16, 16, 16, __nv_bfloat16, wmma::row_major> ah, al;
        wmma::fragment<wmma::matrix_b, 16, 16, 16, __nv_bfloat16, wmma::col_major> bh, bl;

        #pragma unroll
        for (int half = 0; half < 2; half++) {
            // convert current half (regs already loaded), then prefetch next
            cvt_half(buf);
            if (half == 0) {
                ldg_half(tile, 1, buf);
            } else {
                int nt = tile + gridDim.x;
                if (nt < ntiles) ldg_half(nt, 0, buf);
            }
            __syncthreads();     // A half ready

            const __nv_bfloat16* Aw_h = Ahi + (w * 16) * ASTRIDE;
            const __nv_bfloat16* Aw_l = Alo + (w * 16) * ASTRIDE;
            const __nv_bfloat16* Bk_h = Bhi + half * KH;
            const __nv_bfloat16* Bk_l = Blo + half * KH;
            #pragma unroll
            for (int k = 0; k < KH / 16; k++) {
                wmma::load_matrix_sync(ah, Aw_h + k * 16, ASTRIDE);
                wmma::load_matrix_sync(al, Aw_l + k * 16, ASTRIDE);
                #pragma unroll
                for (int n = 0; n < 2; n++) {
                    wmma::load_matrix_sync(bh, Bk_h + n * 16 * BSTRIDE + k * 16, BSTRIDE);
                    wmma::load_matrix_sync(bl, Bk_l + n * 16 * BSTRIDE + k * 16, BSTRIDE);
                    wmma::mma_sync(C[n], ah, bh, C[n]);
                    wmma::mma_sync(C[n], al, bh, C[n]);
                    wmma::mma_sync(C[n], ah, bl, C[n]);
                }
            }
            __syncthreads();     // A consumed; next convert may overwrite
        }

        // nrf % TILE_RF == 0 -> no tail handling
        int rf0 = tile * TILE_RF + w * 16;
        wmma::store_matrix_sync(g_scratch + (size_t)rf0 * 32,      C[0], 32, wmma::mem_row_major);
        wmma::store_matrix_sync(g_scratch + (size_t)rf0 * 32 + 16, C[1], 32, wmma::mem_row_major);
    }
}

// ================= kernel 2: epilogue (LN + attention + MLP) =================
constexpr int WSTRIDE = 36;

__device__ __forceinline__ void ffma2(u64& d, u64 a, u64 b) {
    asm("fma.rn.f32x2 %0, %1, %2, %0;" : "+l"(d) : "l"(a), "l"(b));
}
__device__ __forceinline__ float hsum2(u64 a, u64 b) {
    return __uint_as_float((unsigned)a) + __uint_as_float((unsigned)(a >> 32))
         + __uint_as_float((unsigned)b) + __uint_as_float((unsigned)(b >> 32));
}
__device__ __forceinline__ float wsum(float v) {
    v += __shfl_xor_sync(FULL_MASK, v, 16);
    v += __shfl_xor_sync(FULL_MASK, v, 8);
    v += __shfl_xor_sync(FULL_MASK, v, 4);
    v += __shfl_xor_sync(FULL_MASK, v, 2);
    v += __shfl_xor_sync(FULL_MASK, v, 1);
    return v;
}

__global__ __launch_bounds__(256)
void epi_kernel(const float* __restrict__ bp,
                const float* __restrict__ ln_g, const float* __restrict__ ln_b,
                const float* __restrict__ Wq,  const float* __restrict__ bq,
                const float* __restrict__ Wk,  const float* __restrict__ bk,
                const float* __restrict__ Wv,  const float* __restrict__ bv,
                const float* __restrict__ Wo1, const float* __restrict__ bo1,
                const float* __restrict__ Wo2, const float* __restrict__ bo2,
                float* __restrict__ out, int B)
{
    __shared__ __align__(16) float w5[5 * D * WSTRIDE];
    __shared__ __align__(16) float xbuf[8][3][D];
    __shared__ __align__(16) float pooled[8][D];
    __shared__ __align__(16) float o1s[8][D];

    const int tid = threadIdx.x, lane = tid & 31, w = tid >> 5;

    for (int i = tid; i < D * D; i += 256) {
        int jj = i >> 5, dd = i & 31;
        int o = jj * WSTRIDE + dd;
        w5[0 * D * WSTRIDE + o] = Wq [i];
        w5[1 * D * WSTRIDE + o] = Wk [i];
        w5[2 * D * WSTRIDE + o] = Wv [i];
        w5[3 * D * WSTRIDE + o] = Wo1[i];
        w5[4 * D * WSTRIDE + o] = Wo2[i];
    }
    const float bp_l  = bp [lane];
    const float g_l   = ln_g[lane];
    const float b_l   = ln_b[lane];
    const float bq_l  = bq [lane];
    const float bk_l  = bk [lane];
    const float bv_l  = bv [lane];
    const float bo1_l = bo1[lane];
    const float bo2_l = bo2[lane];
    __syncthreads();

    for (int row = blockIdx.x * 8 + w; row < B; row += gridDim.x * 8) {
        // ---- bias + relu + LayerNorm ----
        #pragma unroll
        for (int s = 0; s < 3; s++) {
            float h = g_scratch[(size_t)(row * 3 + s) * D + lane] + bp_l;
            h = fmaxf(h, 0.f);
            float mu  = wsum(h) * (1.f / 32.f);
            float dv  = h - mu;
            float var = wsum(dv * dv) * (1.f / 32.f);
            xbuf[w][s][lane] = g_l * dv * rsqrtf(var + LN_EPS) + b_l;
        }
        __syncwarp();

        // ---- QKV ----
        float qkvr[3][3];
        float bias3[3] = { bq_l, bk_l, bv_l };
        #pragma unroll
        for (int mat = 0; mat < 3; mat++) {
            const ulonglong2* wrow = reinterpret_cast<const ulonglong2*>(
                w5 + mat * D * WSTRIDE + lane * WSTRIDE);
            u64 a0[3] = {0ull,0ull,0ull}, a1[3] = {0ull,0ull,0ull};
            #pragma unroll
            for (int c = 0; c < 8; c++) {
                ulonglong2 wv = wrow[c];
                #pragma unroll
                for (int ss = 0; ss < 3; ss++) {
                    ulonglong2 xv = reinterpret_cast<const ulonglong2*>(xbuf[w][ss])[c];
                    ffma2(a0[ss], wv.x, xv.x);
                    ffma2(a1[ss], wv.y, xv.y);
                }
            }
            #pragma unroll
            for (int ss = 0; ss < 3; ss++)
                qkvr[mat][ss] = hsum2(a0[ss], a1[ss]) + bias3[mat];
        }

        // ---- attention + softmax + pool ----
        const float scale = 0.17677669529663687f;   // 1/sqrt(32)
        float att[3][3];
        #pragma unroll
        for (int ss = 0; ss < 3; ss++)
            #pragma unroll
            for (int tt = 0; tt < 3; tt++)
                att[ss][tt] = wsum(qkvr[0][ss] * qkvr[1][tt]) * scale;

        float pool = 0.f;
        #pragma unroll
        for (int ss = 0; ss < 3; ss++) {
            float m  = fmaxf(att[ss][0], fmaxf(att[ss][1], att[ss][2]));
            float e0 = __expf(att[ss][0] - m);
            float e1 = __expf(att[ss][1] - m);
            float e2 = __expf(att[ss][2] - m);
            float ri = 1.f / (e0 + e1 + e2);
            pool += (e0 * qkvr[2][0] + e1 * qkvr[2][1] + e2 * qkvr[2][2]) * ri;
        }
        pool *= (1.f / 3.f);
        pooled[w][lane] = pool;
        __syncwarp();

        // ---- O1 ----
        {
            const ulonglong2* pv = reinterpret_cast<const ulonglong2*>(pooled[w]);
            const ulonglong2* w1 = reinterpret_cast<const ulonglong2*>(
                w5 + 3 * D * WSTRIDE + lane * WSTRIDE);
            u64 a0 = 0ull, a1 = 0ull;
            #pragma unroll
            for (int c = 0; c < 8; c++) {
                ulonglong2 pvv = pv[c], wv = w1[c];
                ffma2(a0, wv.x, pvv.x);
                ffma2(a1, wv.y, pvv.y);
            }
            o1s[w][lane] = fmaxf(hsum2(a0, a1) + bo1_l, 0.f);
        }
        __syncwarp();

        // ---- O2 + residual ----
        {
            const ulonglong2* ov = reinterpret_cast<const ulonglong2*>(o1s[w]);
            const ulonglong2* w2 = reinterpret_cast<const ulonglong2*>(
                w5 + 4 * D * WSTRIDE + lane * WSTRIDE);
            u64 a0 = 0ull, a1 = 0ull;
            #pragma unroll
            for (int c = 0; c < 8; c++) {
                ulonglong2 ovv = ov[c], wv = w2[c];
                ffma2(a0, wv.x, ovv.x);
                ffma2(a1, wv.y, ovv.y);
            }
            out[(size_t)row * D + lane] = hsum2(a0, a1) + bo2_l + pool;
        }
        __syncwarp();
    }
}

// ================= launch =================
extern "C" void kernel_launch(void* const* d_in, const int* in_sizes, int n_in,
                              void* d_out, int out_size)
{
    const float* f1   = (const float*)d_in[0];
    const float* f4   = (const float*)d_in[1];
    const float* fD   = (const float*)d_in[2];
    const float* Wp   = (const float*)d_in[3];
    const float* bp   = (const float*)d_in[4];
    const float* ln_g = (const float*)d_in[5];
    const float* ln_b = (const float*)d_in[6];
    const float* Wq   = (const float*)d_in[7];
    const float* bq   = (const float*)d_in[8];
    const float* Wk   = (const float*)d_in[9];
    const float* bk   = (const float*)d_in[10];
    const float* Wv   = (const float*)d_in[11];
    const float* bv   = (const float*)d_in[12];
    const float* Wo1  = (const float*)d_in[13];
    const float* bo1  = (const float*)d_in[14];
    const float* Wo2  = (const float*)d_in[15];
    const float* bo2  = (const float*)d_in[16];

    const int B = in_sizes[0] / IN_DIM;
    const int nrf = B * 3;                       // 196608 = 1536 * 128
    const int ntiles = (nrf + TILE_RF - 1) / TILE_RF;

    cudaFuncSetAttribute(proj_kernel, cudaFuncAttributeMaxDynamicSharedMemorySize, SMEM1);

    int grid1 = ntiles < 304 ? ntiles : 304;     // 2 blocks x 152 SMs
    proj_kernel<<<grid1, THREADS1, SMEM1>>>(f1, f4, fD, Wp, nrf, ntiles);

    int grid2 = (B + 7) / 8;
    if (grid2 > 1216) grid2 = 1216;
    epi_kernel<<<grid2, 256>>>(bp, ln_g, ln_b, Wq, bq, Wk, bk, Wv, bv,
                               Wo1, bo1, Wo2, bo2, (float*)d_out, B);
}